// round 9
// baseline (speedup 1.0000x reference)
#include <cuda_runtime.h>

#define C_FEAT 64
#define NXc 432
#define NYc 496
#define S_CELLS (NXc * NYc)      // 214272 cells per batch element
#define SQ4 (S_CELLS / 4)        // float4 groups per batch/channel row (53568, % 32 == 0)
#define MAXB 8

// Scratch: cell -> (local pillar index + 1), 0 = empty.
// Zero-initialized at module load; gather_kernel restores zeros after use,
// so the empty-map invariant holds before every kernel_launch call.
__device__ unsigned short g_map16[MAXB * S_CELLS];

__global__ void scatter_idx_kernel(const int* __restrict__ coords, int P, int Ppb, int ncells) {
    int p = blockIdx.x * blockDim.x + threadIdx.x;
    if (p >= P) return;
    int4 c = ((const int4*)coords)[p];   // (b, z, y, x) int32
    int flat = c.x * S_CELLS + c.y + c.z * NXc + c.w;
    int local = p - c.x * Ppb;           // per-batch pillar index
    if (flat >= 0 && flat < ncells && local >= 0 && local < 0xFFFF) {
        g_map16[flat] = (unsigned short)(local + 1);
    }
}

// Block (32, 8): x = spatial float4-group (32 consecutive), y = channel slice
// (8 channels = 2 float4-groups each). Grid covers B*SQ4 exactly.
// ALL indexing is 32-bit: out has <= 27.4M float4, feat <= 8.19M floats.
__global__ void __launch_bounds__(256) gather_kernel(
    const float4* __restrict__ feat4,   // [P, 16] float4
    float4* __restrict__ out4,          // [B, 64, SQ4] float4
    unsigned Ppb)
{
    unsigned t = blockIdx.x * 32u + threadIdx.x;   // global q-group index
    unsigned s = threadIdx.y;                      // channel slice 0..7

    unsigned b = t / SQ4;
    unsigned q = t - b * SQ4;

    // One 8B load = 4 uint16 map entries (0 = empty, else local+1)
    uint2* mp = ((uint2*)(g_map16 + b * S_CELLS)) + q;
    uint2 mraw = *mp;

    // All 8 slices read before slice 0 resets.
    __syncthreads();
    if (s == 0 && (mraw.x | mraw.y)) {
        *mp = make_uint2(0u, 0u);
    }

    unsigned m0 = mraw.x & 0xFFFFu, m1 = mraw.x >> 16;
    unsigned m2 = mraw.y & 0xFFFFu, m3 = mraw.y >> 16;

    // 32-bit float4 offsets into feat4 (16 float4 per pillar row)
    unsigned pb16 = b * Ppb * 16u;
    unsigned o0 = pb16 + (m0 - 1u) * 16u;
    unsigned o1 = pb16 + (m1 - 1u) * 16u;
    unsigned o2 = pb16 + (m2 - 1u) * 16u;
    unsigned o3 = pb16 + (m3 - 1u) * 16u;

    unsigned obase = b * (C_FEAT * SQ4) + q;       // 32-bit output offset
    const float4 z4 = make_float4(0.f, 0.f, 0.f, 0.f);

#pragma unroll
    for (unsigned i = 0; i < 2; ++i) {
        unsigned c4 = 2u * s + i;                  // this thread's float4-channel-group
        // plain derefs -> predicated LDG (no branches)
        float4 a  = (m0 != 0u) ? feat4[o0 + c4] : z4;
        float4 bb = (m1 != 0u) ? feat4[o1 + c4] : z4;
        float4 cc = (m2 != 0u) ? feat4[o2 + c4] : z4;
        float4 dd = (m3 != 0u) ? feat4[o3 + c4] : z4;

        // 4x4 register transpose: warp writes 32 consecutive float4 (512B) per row
        unsigned orow = obase + (4u * c4) * SQ4;
        __stcs(out4 + orow,            make_float4(a.x, bb.x, cc.x, dd.x));
        __stcs(out4 + orow + SQ4,      make_float4(a.y, bb.y, cc.y, dd.y));
        __stcs(out4 + orow + 2u * SQ4, make_float4(a.z, bb.z, cc.z, dd.z));
        __stcs(out4 + orow + 3u * SQ4, make_float4(a.w, bb.w, cc.w, dd.w));
    }
}

extern "C" void kernel_launch(void* const* d_in, const int* in_sizes, int n_in,
                              void* d_out, int out_size) {
    const float* feat   = (const float*)d_in[0];
    const int*   coords = (const int*)d_in[1];

    int P = in_sizes[0] / C_FEAT;                 // number of pillars
    int B = out_size / (C_FEAT * S_CELLS);        // batch size from output shape
    if (B > MAXB) B = MAXB;
    int Ppb = P / B;

    int ncells = B * S_CELLS;
    scatter_idx_kernel<<<(P + 255) / 256, 256>>>(coords, P, Ppb, ncells);

    dim3 blk(32, 8);
    int nblocks = (B * SQ4) / 32;                 // exact: SQ4 % 32 == 0
    gather_kernel<<<nblocks, blk>>>((const float4*)feat, (float4*)d_out, (unsigned)Ppb);
}